// round 11
// baseline (speedup 1.0000x reference)
#include <cuda_runtime.h>
#include <cuda_bf16.h>
#include <math.h>

// Dimensions (fixed by the problem)
#define B_ROWS 512
#define D_IN 5
#define H_DIM 128
#define VF_DIM 256
#define L_SEG 62        // LS-1
#define LAB 10
#define NSTEP 20
#define RB 4            // rows per CTA
#define NCTA (B_ROWS / RB)   // 128
#define NTHR 512

typedef unsigned long long ull_t;

// Precomputed global scratch (device globals: no allocation allowed)
__device__ float g_W1t[H_DIM * VF_DIM];          // [k=128][c=256]
__device__ float g_W2t[VF_DIM * VF_DIM];         // [k=256][c=256]
__device__ float g_Wm[32 * VF_DIM * H_DIM];      // [idx][v=256][h=128]  4 MB
__device__ float g_bm[32 * H_DIM];               // [idx][h]
__device__ float g_delta[32];                    // interval widths
__device__ int   g_idx[2 * NSTEP];               // 0-based logsig row per eval

// ---------------------------------------------------------------------------
// f32x2 packed-FMA helpers (sm_103a FFMA2 — PTX-only)
// ---------------------------------------------------------------------------
__device__ __forceinline__ ull_t dup2(float x) {
    ull_t r;
    unsigned int u = __float_as_uint(x);
    asm("mov.b64 %0, {%1, %1};" : "=l"(r) : "r"(u));
    return r;
}
__device__ __forceinline__ void fma2(ull_t& acc, ull_t a, ull_t b) {
    asm("fma.rn.f32x2 %0, %1, %2, %0;" : "+l"(acc) : "l"(a), "l"(b));
}
__device__ __forceinline__ void unpk(ull_t v, float& a, float& b) {
    unsigned int lo, hi;
    asm("mov.b64 {%0, %1}, %2;" : "=r"(lo), "=r"(hi) : "l"(v));
    a = __uint_as_float(lo);
    b = __uint_as_float(hi);
}

// ---------------------------------------------------------------------------
// Setup kernel (merged prep + wmeff).  grid = 160 x 256.  All fp32.
// ---------------------------------------------------------------------------
__global__ void __launch_bounds__(256) setup_kernel(
    const float* __restrict__ ts,
    const float* __restrict__ intervals,
    const float* __restrict__ W1,      // [256][128]
    const float* __restrict__ W2,      // [256][256]
    const float* __restrict__ logsig,  // [32][63]
    const float* __restrict__ Wm,      // [7936][256]
    const float* __restrict__ bm)      // [7936]
{
    if (blockIdx.x < 128) {
        __shared__ float ls[32 * L_SEG];
        int h = blockIdx.x;
        int v = threadIdx.x;

        for (int i = threadIdx.x; i < 32 * L_SEG; i += blockDim.x) {
            int row = i / L_SEG, l = i % L_SEG;
            ls[i] = logsig[row * 63 + l + 1];
        }
        __syncthreads();

        float acc[32];
        #pragma unroll
        for (int i = 0; i < 32; i++) acc[i] = 0.0f;

        for (int l = 0; l < L_SEG; l++) {
            float w = __ldg(&Wm[(h * L_SEG + l) * VF_DIM + v]);
            #pragma unroll
            for (int i = 0; i < 32; i++) acc[i] += w * ls[i * L_SEG + l];
        }
        #pragma unroll
        for (int i = 0; i < 32; i++)
            g_Wm[i * (VF_DIM * H_DIM) + v * H_DIM + h] = acc[i];

        if (threadIdx.x < 32) {
            int i = threadIdx.x;
            float s = 0.0f;
            for (int l = 0; l < L_SEG; l++)
                s += __ldg(&bm[h * L_SEG + l]) * ls[i * L_SEG + l];
            g_bm[i * H_DIM + h] = s;
        }
    } else {
        int b = blockIdx.x - 128;              // 0..31
        int gtid = b * 256 + threadIdx.x;      // 0..8191
        int gsz  = 32 * 256;

        for (int i = gtid; i < H_DIM * VF_DIM; i += gsz) {
            int k = i >> 8, c = i & 255;
            g_W1t[i] = W1[c * H_DIM + k];
        }
        for (int i = gtid; i < VF_DIM * VF_DIM; i += gsz) {
            int k = i >> 8, c = i & 255;
            g_W2t[i] = W2[c * VF_DIM + k];
        }
        if (b == 0) {
            if (threadIdx.x < 32)
                g_delta[threadIdx.x] = intervals[threadIdx.x + 1] - intervals[threadIdx.x];
            if (threadIdx.x < 2 * NSTEP) {
                // Replicate reference fp32 exactly
                float t0 = ts[0];
                float dt = (ts[32] - t0) / 20.0f;
                int i = threadIdx.x >> 1;
                float t = t0 + (float)i * dt;
                if (threadIdx.x & 1) t = t + dt;
                int cnt = 0;
                #pragma unroll
                for (int j = 1; j <= 32; j++) cnt += (intervals[j] < t) ? 1 : 0;
                int idx = cnt + 1;
                idx = max(1, min(idx, 32));
                g_idx[threadIdx.x] = idx - 1;
            }
        }
    }
}

// ---------------------------------------------------------------------------
// One k-iter: float4 weight (4 cols), ull2 acts (4 rows), 8 FFMA2.
// acc[ci][rp]: rp 0 = rows (0,1), rp 1 = rows (2,3)
// ---------------------------------------------------------------------------
__device__ __forceinline__ void mac4(
    float4 w, ulonglong2 av, ull_t acc[4][2])
{
    ull_t d;
    d = dup2(w.x); fma2(acc[0][0], d, av.x); fma2(acc[0][1], d, av.y);
    d = dup2(w.y); fma2(acc[1][0], d, av.x); fma2(acc[1][1], d, av.y);
    d = dup2(w.z); fma2(acc[2][0], d, av.x); fma2(acc[2][1], d, av.y);
    d = dup2(w.w); fma2(acc[3][0], d, av.x); fma2(acc[3][1], d, av.y);
}

// Store accumulators to partial buffer (ci-major, contiguous per warp).
// pbase = p_s + s*(C*4) + cg*4 ; column ci at +ci*C
template <int C>
__device__ __forceinline__ void store_partials(float* pbase, ull_t acc[4][2])
{
    #pragma unroll
    for (int ci = 0; ci < 4; ci++) {
        float v0, v1, v2, v3;
        unpk(acc[ci][0], v0, v1);
        unpk(acc[ci][1], v2, v3);
        *(float4*)(pbase + ci * C) = make_float4(v0, v1, v2, v3);
    }
}

// ---------------------------------------------------------------------------
// Persistent integration kernel: 128 CTAs x 512 threads, 4 rows per CTA.
// 4 cols x 4 rows per thread, LDG.128 weights, split-K 8/8/16.
// ---------------------------------------------------------------------------
#define SMEM_FLOATS (512 + 512 + 512 + 1024 + 1024 + 8192)   // 11776 = 47104 B

__global__ void __launch_bounds__(NTHR, 1)
integrate_kernel(const float* __restrict__ x0,     // [512][5]
                 const float* __restrict__ W_in,   // [128][5]
                 const float* __restrict__ b_in,   // [128]
                 const float* __restrict__ b1,     // [256]
                 const float* __restrict__ b2,     // [256]
                 const float* __restrict__ W_out,  // [10][128]
                 const float* __restrict__ b_out,  // [10]
                 const float* __restrict__ ts,
                 float* __restrict__ out)          // [512][10]
{
    extern __shared__ __align__(16) float sm[];
    float* y_s  = sm;                    // 512   : y   [h=128][r=4]
    float* yt_s = y_s + 512;             // 512
    float* k1_s = yt_s + 512;            // 512
    float* h1_s = k1_s + 512;            // 1024  : [c=256][r=4]
    float* h2_s = h1_s + 1024;           // 1024
    float* p_s  = h2_s + 1024;           // 8192  : split-K partials

    const int tid = threadIdx.x;
    const int r0  = blockIdx.x * RB;
    // Layers 1/2: 64 col-groups (4 cols) x 8 K-slices
    const int cg  = tid & 63;
    const int s   = tid >> 6;            // 0..7
    // Layer 3: 32 col-groups x 16 K-slices
    const int cg3 = tid & 31;
    const int s3  = tid >> 5;            // 0..15

    // Weight base pointers (float4 = 4 cols)
    const float* wp1 = g_W1t + (s * 16) * VF_DIM + cg * 4;    // k-range 16
    const float* wp2 = g_W2t + (s * 32) * VF_DIM + cg * 4;    // k-range 32
    // wp3 depends on kt (per eval)

    // Partial-store bases (ci-major layout)
    float* pb12 = p_s + s * 1024 + cg * 4;     // + ci*256
    float* pb3  = p_s + s3 * 512 + cg3 * 4;    // + ci*128

    // y0 = x0 @ W_in^T + b_in   (one (h, r) per thread)
    {
        int h = tid >> 2, r = tid & 3;
        float acc = __ldg(&b_in[h]);
        #pragma unroll
        for (int d = 0; d < D_IN; d++)
            acc += __ldg(&x0[(r0 + r) * D_IN + d]) * __ldg(&W_in[h * D_IN + d]);
        y_s[tid] = acc;
    }
    const float dt = (ts[32] - ts[0]) / 20.0f;

    float4 w1buf[4];
    #pragma unroll
    for (int j = 0; j < 4; j++) w1buf[j] = *(const float4*)(wp1 + j * VF_DIM);
    __syncthreads();

    for (int step = 0; step < NSTEP; step++) {
        #pragma unroll 1
        for (int phase = 0; phase < 2; phase++) {
            const float* in_s = phase ? yt_s : y_s;
            const int kt = g_idx[2 * step + phase];
            const float* wp3 = g_Wm + kt * (VF_DIM * H_DIM) + (s3 * 16) * H_DIM + cg3 * 4;

            float4 w2buf[4];
            float4 w3buf[4];

            // ==== Layer 1 GEMM: K=128, 8 slices x 16 k, smem-act broadcast ====
            {
                const float* ap = in_s + (s * 16) * 4;
                ull_t acc[4][2];
                #pragma unroll
                for (int ci = 0; ci < 4; ci++) { acc[ci][0] = 0ull; acc[ci][1] = 0ull; }
                #pragma unroll
                for (int kb = 0; kb < 16; kb += 4) {
                    #pragma unroll
                    for (int j = 0; j < 4; j++) {
                        float4 wn = w1buf[j];
                        int nk = kb + 4 + j;
                        if (nk < 16) wn = *(const float4*)(wp1 + nk * VF_DIM);
                        ulonglong2 av = *(const ulonglong2*)(ap + (kb + j) * 4);
                        mac4(w1buf[j], av, acc);
                        w1buf[j] = wn;
                    }
                }
                store_partials<VF_DIM>(pb12, acc);
            }
            // Prefetch layer-2 weights (hides L2 latency behind barrier+reduce)
            #pragma unroll
            for (int j = 0; j < 4; j++) w2buf[j] = *(const float4*)(wp2 + j * VF_DIM);
            __syncthreads();

            // ==== Reduce 1 (512 threads, one (c, row-pair) each): bias+relu ====
            {
                int c = tid & 255, rp = (tid >> 8) * 2;
                int off = (c & 3) * 256 + (c >> 2) * 4 + rp;
                float a0 = 0.f, a1 = 0.f;
                #pragma unroll
                for (int ss = 0; ss < 8; ss++) {
                    float2 q = *(const float2*)&p_s[ss * 1024 + off];
                    a0 += q.x; a1 += q.y;
                }
                float bb = __ldg(&b1[c]);
                *(float2*)&h1_s[c * 4 + rp] =
                    make_float2(fmaxf(a0 + bb, 0.f), fmaxf(a1 + bb, 0.f));
            }
            __syncthreads();

            // ==== Layer 2 GEMM: K=256, 8 slices x 32 k, pipelined LDG.128 ====
            {
                const float* ap = h1_s + (s * 32) * 4;
                ull_t acc[4][2];
                #pragma unroll
                for (int ci = 0; ci < 4; ci++) { acc[ci][0] = 0ull; acc[ci][1] = 0ull; }
                #pragma unroll
                for (int kb = 0; kb < 32; kb += 4) {
                    #pragma unroll
                    for (int j = 0; j < 4; j++) {
                        float4 wn = w2buf[j];
                        int nk = kb + 4 + j;
                        if (nk < 32) wn = *(const float4*)(wp2 + nk * VF_DIM);
                        ulonglong2 av = *(const ulonglong2*)(ap + (kb + j) * 4);
                        mac4(w2buf[j], av, acc);
                        w2buf[j] = wn;
                    }
                }
                store_partials<VF_DIM>(pb12, acc);
            }
            // Prefetch layer-3 weights
            #pragma unroll
            for (int j = 0; j < 4; j++) w3buf[j] = *(const float4*)(wp3 + j * H_DIM);
            __syncthreads();

            // ==== Reduce 2 (512 threads): bias + tanh ====
            {
                int c = tid & 255, rp = (tid >> 8) * 2;
                int off = (c & 3) * 256 + (c >> 2) * 4 + rp;
                float a0 = 0.f, a1 = 0.f;
                #pragma unroll
                for (int ss = 0; ss < 8; ss++) {
                    float2 q = *(const float2*)&p_s[ss * 1024 + off];
                    a0 += q.x; a1 += q.y;
                }
                float bb = __ldg(&b2[c]);
                *(float2*)&h2_s[c * 4 + rp] =
                    make_float2(tanhf(a0 + bb), tanhf(a1 + bb));
            }
            __syncthreads();

            // ==== Layer 3 GEMM: K=256, 16 slices x 16 k, C=128 ====
            {
                const float* ap = h2_s + (s3 * 16) * 4;
                ull_t acc[4][2];
                #pragma unroll
                for (int ci = 0; ci < 4; ci++) { acc[ci][0] = 0ull; acc[ci][1] = 0ull; }
                #pragma unroll
                for (int kb = 0; kb < 16; kb += 4) {
                    #pragma unroll
                    for (int j = 0; j < 4; j++) {
                        float4 wn = w3buf[j];
                        int nk = kb + 4 + j;
                        if (nk < 16) wn = *(const float4*)(wp3 + nk * H_DIM);
                        ulonglong2 av = *(const ulonglong2*)(ap + (kb + j) * 4);
                        mac4(w3buf[j], av, acc);
                        w3buf[j] = wn;
                    }
                }
                store_partials<H_DIM>(pb3, acc);
            }
            // Prefetch layer-1 weights for the next phase
            #pragma unroll
            for (int j = 0; j < 4; j++) w1buf[j] = *(const float4*)(wp1 + j * VF_DIM);
            __syncthreads();

            // ==== Reduce 3 + Heun (one (h, r) per thread) ====
            {
                int h = tid >> 2, r = tid & 3;
                int off = (h & 3) * 128 + (h >> 2) * 4 + r;
                float a = 0.f;
                #pragma unroll
                for (int ss = 0; ss < 16; ss++)
                    a += p_s[ss * 512 + off];
                float dl  = g_delta[kt];
                float bmv = g_bm[kt * H_DIM + h];
                float d = (a + bmv) / dl;
                if (phase == 0) {
                    k1_s[tid] = d;
                    yt_s[tid] = y_s[tid] + dt * d;
                } else {
                    y_s[tid] = y_s[tid] + 0.5f * dt * (k1_s[tid] + d);
                }
            }
            __syncthreads();
        }
    }

    // ---- Output: softmax(y @ W_out^T + b_out), 4 rows x 10 labels ----
    if (tid < RB * LAB) {
        int lab = tid % LAB, r = tid / LAB;
        float acc = __ldg(&b_out[lab]);
        for (int k = 0; k < H_DIM; k++)
            acc += y_s[k * RB + r] * __ldg(&W_out[lab * H_DIM + k]);
        h1_s[r * LAB + lab] = acc;
    }
    __syncthreads();
    if (tid < RB) {
        int r = tid;
        float mx = -1e30f;
        #pragma unroll
        for (int l = 0; l < LAB; l++) mx = fmaxf(mx, h1_s[r * LAB + l]);
        float e[LAB]; float sum = 0.f;
        #pragma unroll
        for (int l = 0; l < LAB; l++) { e[l] = expf(h1_s[r * LAB + l] - mx); sum += e[l]; }
        #pragma unroll
        for (int l = 0; l < LAB; l++) out[(r0 + r) * LAB + l] = e[l] / sum;
    }
}

// ---------------------------------------------------------------------------
extern "C" void kernel_launch(void* const* d_in, const int* in_sizes, int n_in,
                              void* d_out, int out_size)
{
    const float* ts        = (const float*)d_in[0];
    const float* logsig    = (const float*)d_in[1];
    const float* x0        = (const float*)d_in[2];
    const float* intervals = (const float*)d_in[3];
    const float* W_vf1     = (const float*)d_in[4];
    const float* b_vf1     = (const float*)d_in[5];
    const float* W_vf2     = (const float*)d_in[6];
    const float* b_vf2     = (const float*)d_in[7];
    const float* W_m       = (const float*)d_in[8];
    const float* b_m       = (const float*)d_in[9];
    const float* W_in      = (const float*)d_in[10];
    const float* b_in      = (const float*)d_in[11];
    const float* W_out     = (const float*)d_in[12];
    const float* b_out     = (const float*)d_in[13];
    float* out = (float*)d_out;

    size_t smem_bytes = SMEM_FLOATS * sizeof(float);  // 47104 B
    cudaFuncSetAttribute(integrate_kernel,
                         cudaFuncAttributeMaxDynamicSharedMemorySize,
                         (int)smem_bytes);

    setup_kernel<<<160, 256>>>(ts, intervals, W_vf1, W_vf2, logsig, W_m, b_m);
    integrate_kernel<<<NCTA, NTHR, smem_bytes>>>(x0, W_in, b_in, b_vf1, b_vf2,
                                                 W_out, b_out, ts, out);
}

// round 12
// speedup vs baseline: 1.1712x; 1.1712x over previous
#include <cuda_runtime.h>
#include <cuda_bf16.h>
#include <math.h>

// Dimensions (fixed by the problem)
#define B_ROWS 512
#define D_IN 5
#define H_DIM 128
#define VF_DIM 256
#define L_SEG 62        // LS-1
#define LAB 10
#define NSTEP 20
#define RB 4            // rows per CTA
#define NCTA (B_ROWS / RB)   // 128
#define NTHR 512

typedef unsigned long long ull_t;

// Precomputed global scratch (device globals: no allocation allowed)
__device__ float g_W1t[H_DIM * VF_DIM];          // [k=128][c=256]
__device__ float g_W2t[VF_DIM * VF_DIM];         // [k=256][c=256]
__device__ float g_Wm[32 * VF_DIM * H_DIM];      // [idx][v=256][h=128]  4 MB
__device__ float g_bm[32 * H_DIM];               // [idx][h]
__device__ float g_delta[32];                    // interval widths
__device__ int   g_idx[2 * NSTEP];               // 0-based logsig row per eval

// ---------------------------------------------------------------------------
// f32x2 packed-FMA helpers (sm_103a FFMA2 — PTX-only)
// ---------------------------------------------------------------------------
__device__ __forceinline__ ull_t dup2(float x) {
    ull_t r;
    unsigned int u = __float_as_uint(x);
    asm("mov.b64 %0, {%1, %1};" : "=l"(r) : "r"(u));
    return r;
}
__device__ __forceinline__ void fma2(ull_t& acc, ull_t a, ull_t b) {
    asm("fma.rn.f32x2 %0, %1, %2, %0;" : "+l"(acc) : "l"(a), "l"(b));
}
__device__ __forceinline__ void unpk(ull_t v, float& a, float& b) {
    unsigned int lo, hi;
    asm("mov.b64 {%0, %1}, %2;" : "=r"(lo), "=r"(hi) : "l"(v));
    a = __uint_as_float(lo);
    b = __uint_as_float(hi);
}

// ---------------------------------------------------------------------------
// Setup kernel (merged prep + wmeff).  grid = 160 x 256.  All fp32.
// ---------------------------------------------------------------------------
__global__ void __launch_bounds__(256) setup_kernel(
    const float* __restrict__ ts,
    const float* __restrict__ intervals,
    const float* __restrict__ W1,      // [256][128]
    const float* __restrict__ W2,      // [256][256]
    const float* __restrict__ logsig,  // [32][63]
    const float* __restrict__ Wm,      // [7936][256]
    const float* __restrict__ bm)      // [7936]
{
    if (blockIdx.x < 128) {
        __shared__ float ls[32 * L_SEG];
        int h = blockIdx.x;
        int v = threadIdx.x;

        for (int i = threadIdx.x; i < 32 * L_SEG; i += blockDim.x) {
            int row = i / L_SEG, l = i % L_SEG;
            ls[i] = logsig[row * 63 + l + 1];
        }
        __syncthreads();

        float acc[32];
        #pragma unroll
        for (int i = 0; i < 32; i++) acc[i] = 0.0f;

        for (int l = 0; l < L_SEG; l++) {
            float w = __ldg(&Wm[(h * L_SEG + l) * VF_DIM + v]);
            #pragma unroll
            for (int i = 0; i < 32; i++) acc[i] += w * ls[i * L_SEG + l];
        }
        #pragma unroll
        for (int i = 0; i < 32; i++)
            g_Wm[i * (VF_DIM * H_DIM) + v * H_DIM + h] = acc[i];

        if (threadIdx.x < 32) {
            int i = threadIdx.x;
            float s = 0.0f;
            for (int l = 0; l < L_SEG; l++)
                s += __ldg(&bm[h * L_SEG + l]) * ls[i * L_SEG + l];
            g_bm[i * H_DIM + h] = s;
        }
    } else {
        int b = blockIdx.x - 128;              // 0..31
        int gtid = b * 256 + threadIdx.x;      // 0..8191
        int gsz  = 32 * 256;

        for (int i = gtid; i < H_DIM * VF_DIM; i += gsz) {
            int k = i >> 8, c = i & 255;
            g_W1t[i] = W1[c * H_DIM + k];
        }
        for (int i = gtid; i < VF_DIM * VF_DIM; i += gsz) {
            int k = i >> 8, c = i & 255;
            g_W2t[i] = W2[c * VF_DIM + k];
        }
        if (b == 0) {
            if (threadIdx.x < 32)
                g_delta[threadIdx.x] = intervals[threadIdx.x + 1] - intervals[threadIdx.x];
            if (threadIdx.x < 2 * NSTEP) {
                // Replicate reference fp32 exactly
                float t0 = ts[0];
                float dt = (ts[32] - t0) / 20.0f;
                int i = threadIdx.x >> 1;
                float t = t0 + (float)i * dt;
                if (threadIdx.x & 1) t = t + dt;
                int cnt = 0;
                #pragma unroll
                for (int j = 1; j <= 32; j++) cnt += (intervals[j] < t) ? 1 : 0;
                int idx = cnt + 1;
                idx = max(1, min(idx, 32));
                g_idx[threadIdx.x] = idx - 1;
            }
        }
    }
}

// ---------------------------------------------------------------------------
// One k-iter: float4 weight (4 cols), ull2 acts (4 rows), 8 FFMA2.
// ---------------------------------------------------------------------------
__device__ __forceinline__ void mac4(
    float4 w, ulonglong2 av, ull_t acc[4][2])
{
    ull_t d;
    d = dup2(w.x); fma2(acc[0][0], d, av.x); fma2(acc[0][1], d, av.y);
    d = dup2(w.y); fma2(acc[1][0], d, av.x); fma2(acc[1][1], d, av.y);
    d = dup2(w.z); fma2(acc[2][0], d, av.x); fma2(acc[2][1], d, av.y);
    d = dup2(w.w); fma2(acc[3][0], d, av.x); fma2(acc[3][1], d, av.y);
}

// Conflict-free partial store: region per column ci.
// Slice layout q = ci*CR4 + cg*4 + r  (CR4 = C*R/4).
// Store addr = pbase + ci*CR4 : lanes (consecutive cg) are 16B-contiguous.
template <int CR4>
__device__ __forceinline__ void store_partials(float* pbase, ull_t acc[4][2])
{
    #pragma unroll
    for (int ci = 0; ci < 4; ci++) {
        float v0, v1, v2, v3;
        unpk(acc[ci][0], v0, v1);
        unpk(acc[ci][1], v2, v3);
        *(float4*)(pbase + ci * CR4) = make_float4(v0, v1, v2, v3);
    }
}

// ---------------------------------------------------------------------------
// Persistent integration kernel: 128 CTAs x 512 threads, 4 rows per CTA.
// 4c x 4r tiles, conflict-free partial store+load, depth-4 w/act pipelines.
// ---------------------------------------------------------------------------
#define SMEM_FLOATS (32768 + 512 + 512 + 512 + 1024 + 1024 + 8192)  // 178176 B

__global__ void __launch_bounds__(NTHR, 1)
integrate_kernel(const float* __restrict__ x0,     // [512][5]
                 const float* __restrict__ W_in,   // [128][5]
                 const float* __restrict__ b_in,   // [128]
                 const float* __restrict__ b1,     // [256]
                 const float* __restrict__ b2,     // [256]
                 const float* __restrict__ W_out,  // [10][128]
                 const float* __restrict__ b_out,  // [10]
                 const float* __restrict__ ts,
                 float* __restrict__ out)          // [512][10]
{
    extern __shared__ __align__(16) float sm[];
    float* W1s  = sm;                    // 32768 : W1t cached [k][c]
    float* y_s  = W1s + 32768;           // 512   : y   [h=128][r=4]
    float* yt_s = y_s + 512;             // 512
    float* k1_s = yt_s + 512;            // 512
    float* h1_s = k1_s + 512;            // 1024  : [c=256][r=4]
    float* h2_s = h1_s + 1024;           // 1024
    float* p_s  = h2_s + 1024;           // 8192  : split-K partials

    const int tid = threadIdx.x;
    const int r0  = blockIdx.x * RB;
    // Layers 1/2: 64 col-groups (4 cols) x 8 K-slices
    const int cg  = tid & 63;
    const int s   = tid >> 6;            // 0..7
    // Layer 3: 32 col-groups x 16 K-slices
    const int cg3 = tid & 31;
    const int s3  = tid >> 5;            // 0..15

    // Weight base pointers
    const float* wp1 = W1s   + (s * 16) * VF_DIM + cg * 4;
    const float* wp2 = g_W2t + (s * 32) * VF_DIM + cg * 4;

    // Partial-store bases (region-per-ci)
    float* pb12 = p_s + s * 1024 + cg * 4;     // + ci*256
    float* pb3  = p_s + s3 * 512 + cg3 * 4;    // + ci*128

    // Cache W1t into shared memory
    for (int i = tid; i < 8192; i += NTHR)
        *(float4*)&W1s[i * 4] = *(const float4*)&g_W1t[i * 4];

    // y0 = x0 @ W_in^T + b_in   (one (h, r) per thread)
    {
        int h = tid >> 2, r = tid & 3;
        float acc = __ldg(&b_in[h]);
        #pragma unroll
        for (int d = 0; d < D_IN; d++)
            acc += __ldg(&x0[(r0 + r) * D_IN + d]) * __ldg(&W_in[h * D_IN + d]);
        y_s[tid] = acc;
    }
    const float dt = (ts[32] - ts[0]) / 20.0f;
    __syncthreads();

    for (int step = 0; step < NSTEP; step++) {
        #pragma unroll 1
        for (int phase = 0; phase < 2; phase++) {
            const float* in_s = phase ? yt_s : y_s;
            const int kt = g_idx[2 * step + phase];
            const float* wp3 = g_Wm + kt * (VF_DIM * H_DIM) + (s3 * 16) * H_DIM + cg3 * 4;

            float4 w2buf[4];
            float4 w3buf[4];

            // ==== Layer 1 GEMM: K=128, 8 slices x 16 k (smem w + smem acts) ====
            {
                const float* ap = in_s + (s * 16) * 4;
                ull_t acc[4][2];
                #pragma unroll
                for (int ci = 0; ci < 4; ci++) { acc[ci][0] = 0ull; acc[ci][1] = 0ull; }
                #pragma unroll
                for (int k = 0; k < 16; k++) {
                    float4 w = *(const float4*)(wp1 + k * VF_DIM);
                    ulonglong2 av = *(const ulonglong2*)(ap + k * 4);
                    mac4(w, av, acc);
                }
                store_partials<256>(pb12, acc);
            }
            // Prefetch layer-2 weights (hides L2 latency behind reduce)
            #pragma unroll
            for (int j = 0; j < 4; j++) w2buf[j] = *(const float4*)(wp2 + j * VF_DIM);
            __syncthreads();

            // ==== Reduce 1: coalesced q=tid reads, permuted write ====
            #pragma unroll
            for (int hf = 0; hf < 2; hf++) {
                int q = hf * 512 + tid;
                float a = 0.f;
                #pragma unroll
                for (int ss = 0; ss < 8; ss++)
                    a += p_s[ss * 1024 + q];
                int ci = q >> 8, rem = q & 255;
                int c = (rem >> 2) * 4 + ci, r = rem & 3;
                h1_s[c * 4 + r] = fmaxf(a + __ldg(&b1[c]), 0.f);
            }
            __syncthreads();

            // ==== Layer 2 GEMM: K=256, 8 slices x 32 k, depth-4 w+act pipe ====
            {
                const float* ap = h1_s + (s * 32) * 4;
                ulonglong2 abuf[4];
                #pragma unroll
                for (int j = 0; j < 4; j++)
                    abuf[j] = *(const ulonglong2*)(ap + j * 4);
                ull_t acc[4][2];
                #pragma unroll
                for (int ci = 0; ci < 4; ci++) { acc[ci][0] = 0ull; acc[ci][1] = 0ull; }
                #pragma unroll
                for (int kb = 0; kb < 32; kb += 4) {
                    #pragma unroll
                    for (int j = 0; j < 4; j++) {
                        float4 wn = w2buf[j];
                        ulonglong2 an = abuf[j];
                        int nk = kb + 4 + j;
                        if (nk < 32) {                    // compile-time resolved
                            wn = *(const float4*)(wp2 + nk * VF_DIM);
                            an = *(const ulonglong2*)(ap + nk * 4);
                        }
                        mac4(w2buf[j], abuf[j], acc);
                        w2buf[j] = wn; abuf[j] = an;
                    }
                }
                store_partials<256>(pb12, acc);
            }
            // Prefetch layer-3 weights
            #pragma unroll
            for (int j = 0; j < 4; j++) w3buf[j] = *(const float4*)(wp3 + j * H_DIM);
            __syncthreads();

            // ==== Reduce 2: bias + tanh ====
            #pragma unroll
            for (int hf = 0; hf < 2; hf++) {
                int q = hf * 512 + tid;
                float a = 0.f;
                #pragma unroll
                for (int ss = 0; ss < 8; ss++)
                    a += p_s[ss * 1024 + q];
                int ci = q >> 8, rem = q & 255;
                int c = (rem >> 2) * 4 + ci, r = rem & 3;
                h2_s[c * 4 + r] = tanhf(a + __ldg(&b2[c]));
            }
            __syncthreads();

            // ==== Layer 3 GEMM: K=256, 16 slices x 16 k, depth-4 w+act pipe ====
            {
                const float* ap = h2_s + (s3 * 16) * 4;
                ulonglong2 abuf[4];
                #pragma unroll
                for (int j = 0; j < 4; j++)
                    abuf[j] = *(const ulonglong2*)(ap + j * 4);
                ull_t acc[4][2];
                #pragma unroll
                for (int ci = 0; ci < 4; ci++) { acc[ci][0] = 0ull; acc[ci][1] = 0ull; }
                #pragma unroll
                for (int kb = 0; kb < 16; kb += 4) {
                    #pragma unroll
                    for (int j = 0; j < 4; j++) {
                        float4 wn = w3buf[j];
                        ulonglong2 an = abuf[j];
                        int nk = kb + 4 + j;
                        if (nk < 16) {
                            wn = *(const float4*)(wp3 + nk * H_DIM);
                            an = *(const ulonglong2*)(ap + nk * 4);
                        }
                        mac4(w3buf[j], abuf[j], acc);
                        w3buf[j] = wn; abuf[j] = an;
                    }
                }
                store_partials<128>(pb3, acc);
            }
            __syncthreads();

            // ==== Reduce 3 + Heun: coalesced q=tid reads, permuted write ====
            {
                int q = tid;
                float a = 0.f;
                #pragma unroll
                for (int ss = 0; ss < 16; ss++)
                    a += p_s[ss * 512 + q];
                int ci = q >> 7, rem = q & 127;
                int h = (rem >> 2) * 4 + ci, r = rem & 3;
                float dl  = g_delta[kt];
                float bmv = g_bm[kt * H_DIM + h];
                float d = (a + bmv) / dl;
                int addr = h * 4 + r;
                if (phase == 0) {
                    k1_s[addr] = d;
                    yt_s[addr] = y_s[addr] + dt * d;
                } else {
                    y_s[addr] = y_s[addr] + 0.5f * dt * (k1_s[addr] + d);
                }
            }
            __syncthreads();
        }
    }

    // ---- Output: softmax(y @ W_out^T + b_out), 4 rows x 10 labels ----
    if (tid < RB * LAB) {
        int lab = tid % LAB, r = tid / LAB;
        float acc = __ldg(&b_out[lab]);
        for (int k = 0; k < H_DIM; k++)
            acc += y_s[k * RB + r] * __ldg(&W_out[lab * H_DIM + k]);
        h1_s[r * LAB + lab] = acc;
    }
    __syncthreads();
    if (tid < RB) {
        int r = tid;
        float mx = -1e30f;
        #pragma unroll
        for (int l = 0; l < LAB; l++) mx = fmaxf(mx, h1_s[r * LAB + l]);
        float e[LAB]; float sum = 0.f;
        #pragma unroll
        for (int l = 0; l < LAB; l++) { e[l] = expf(h1_s[r * LAB + l] - mx); sum += e[l]; }
        #pragma unroll
        for (int l = 0; l < LAB; l++) out[(r0 + r) * LAB + l] = e[l] / sum;
    }
}

// ---------------------------------------------------------------------------
extern "C" void kernel_launch(void* const* d_in, const int* in_sizes, int n_in,
                              void* d_out, int out_size)
{
    const float* ts        = (const float*)d_in[0];
    const float* logsig    = (const float*)d_in[1];
    const float* x0        = (const float*)d_in[2];
    const float* intervals = (const float*)d_in[3];
    const float* W_vf1     = (const float*)d_in[4];
    const float* b_vf1     = (const float*)d_in[5];
    const float* W_vf2     = (const float*)d_in[6];
    const float* b_vf2     = (const float*)d_in[7];
    const float* W_m       = (const float*)d_in[8];
    const float* b_m       = (const float*)d_in[9];
    const float* W_in      = (const float*)d_in[10];
    const float* b_in      = (const float*)d_in[11];
    const float* W_out     = (const float*)d_in[12];
    const float* b_out     = (const float*)d_in[13];
    float* out = (float*)d_out;

    size_t smem_bytes = SMEM_FLOATS * sizeof(float);  // 178176 B
    cudaFuncSetAttribute(integrate_kernel,
                         cudaFuncAttributeMaxDynamicSharedMemorySize,
                         (int)smem_bytes);

    setup_kernel<<<160, 256>>>(ts, intervals, W_vf1, W_vf2, logsig, W_m, b_m);
    integrate_kernel<<<NCTA, NTHR, smem_bytes>>>(x0, W_in, b_in, b_vf1, b_vf2,
                                                 W_out, b_out, ts, out);
}